// round 16
// baseline (speedup 1.0000x reference)
#include <cuda_runtime.h>
#include <cuda_fp16.h>
#include <stdint.h>

// Problem constants (B=4, S=4096, HID=1024, H=16, D=64)
#define GM 16384
#define GN 1024
#define GK 1024
#define NPOS 16384
#define ATT_ELEMS (NPOS * 256)
#define MAIN_OUT_ELEMS (GM * GN)
#define WSLOT ((size_t)GN * GK)

// Device-global scratch (no allocations allowed)
__device__ __align__(16) __half g_Qh[(size_t)GM * GN];
__device__ __align__(16) __half g_Kh[(size_t)GM * GN];
__device__ __align__(16) __half g_Vh[(size_t)GM * GN];
__device__ __align__(16) __half g_Xh[(size_t)GM * GK];   // (B,H,S,D) fp16
__device__ __align__(16) __half g_Wth[4 * WSLOT];        // W^T fp16, slots 0..3

// ---------------------------------------------------------------------------
// helpers
// ---------------------------------------------------------------------------
__device__ __forceinline__ void mma16816(float* c, const uint32_t* a, uint32_t b0, uint32_t b1) {
    asm volatile(
        "mma.sync.aligned.m16n8k16.row.col.f32.f16.f16.f32 "
        "{%0,%1,%2,%3}, {%4,%5,%6,%7}, {%8,%9}, {%0,%1,%2,%3};"
        : "+f"(c[0]), "+f"(c[1]), "+f"(c[2]), "+f"(c[3])
        : "r"(a[0]), "r"(a[1]), "r"(a[2]), "r"(a[3]), "r"(b0), "r"(b1));
}

__device__ __forceinline__ void ldsm4(uint32_t* r, uint32_t addr) {
    asm volatile("ldmatrix.sync.aligned.m8n8.x4.shared.b16 {%0,%1,%2,%3}, [%4];"
                 : "=r"(r[0]), "=r"(r[1]), "=r"(r[2]), "=r"(r[3]) : "r"(addr));
}

__device__ __forceinline__ void ldsm4t(uint32_t* r, uint32_t addr) {
    asm volatile("ldmatrix.sync.aligned.m8n8.x4.trans.shared.b16 {%0,%1,%2,%3}, [%4];"
                 : "=r"(r[0]), "=r"(r[1]), "=r"(r[2]), "=r"(r[3]) : "r"(addr));
}

__device__ __forceinline__ void cp16(uint32_t dst, const void* src) {
    asm volatile("cp.async.cg.shared.global [%0], [%1], 16;" :: "r"(dst), "l"(src));
}

__device__ __forceinline__ uint32_t h2u(__half2 h) { return *reinterpret_cast<uint32_t*>(&h); }

__device__ __forceinline__ float sumsq16(uint4 u) {
    const __half2* h = reinterpret_cast<const __half2*>(&u);
    float s = 0.f;
    #pragma unroll
    for (int i = 0; i < 4; i++) {
        float2 f = __half22float2(h[i]);
        s += f.x * f.x + f.y * f.y;
    }
    return s;
}

// ---------------------------------------------------------------------------
// W split: fp32 [K,N] -> fp16 [N,K] (transpose). blockIdx.z selects W.
// ---------------------------------------------------------------------------
__global__ __launch_bounds__(256) void split_wt4_kernel(
    const float* __restrict__ w0, const float* __restrict__ w1,
    const float* __restrict__ w2, const float* __restrict__ w3)
{
    const int z = blockIdx.z;
    const float* W = (z == 0) ? w0 : (z == 1) ? w1 : (z == 2) ? w2 : w3;
    __half* Wh = g_Wth + (size_t)z * WSLOT;

    __shared__ float t[32][33];
    int n0 = blockIdx.x * 32, k0 = blockIdx.y * 32;
    int tx = threadIdx.x & 31, ty = threadIdx.x >> 5;
    #pragma unroll
    for (int j = 0; j < 4; j++)
        t[ty + 8 * j][tx] = W[(size_t)(k0 + ty + 8 * j) * GN + n0 + tx];
    __syncthreads();
    #pragma unroll
    for (int j = 0; j < 4; j++) {
        int r = ty + 8 * j;
        Wh[(size_t)(n0 + r) * GK + k0 + tx] = __float2half_rn(t[tx][r]);
    }
}

// ---------------------------------------------------------------------------
// GEMM: C = A @ W + bias, fp16 MMA, fp32 accum. 3-stage cp.async ring,
// wait_group 1 keeps one copy in flight across the per-k-tile barrier.
// CTA 128x128, BK=64, 256 threads = 8 warps (2x4), warp tile 64x32.
// ---------------------------------------------------------------------------
#define ROWB     144
#define TILE_B   (128 * ROWB)
#define STAGE_B  (2 * TILE_B)
#define GSMEM    (3 * STAGE_B)       // 110592
#define NKT      16

__device__ __forceinline__ __half* half_out_ptr(int tag) {
    switch (tag) { case 1: return g_Qh; case 2: return g_Kh;
                   case 3: return g_Vh; default: return nullptr; }
}

__global__ __launch_bounds__(256, 1) void gemm_tc_kernel(
    const float* __restrict__ Afp32, int w_slot,
    float* Cout, int c_tag, const float* __restrict__ bias)
{
    const __half* Bh = g_Wth + (size_t)w_slot * WSLOT;

    extern __shared__ __align__(16) char sm[];
    const uint32_t smbase = (uint32_t)__cvta_generic_to_shared(sm);

    const int tid  = threadIdx.x;
    const int warp = tid >> 5;
    const int lane = tid & 31;
    const int gid  = lane >> 2;
    const int tig  = lane & 3;
    const int wm = (warp >> 2) * 64;
    const int wn = (warp & 3) * 32;
    const int bm = blockIdx.y * 128;
    const int bn = blockIdx.x * 128;

    float acc[4][4][4];
    #pragma unroll
    for (int a = 0; a < 4; a++)
        #pragma unroll
        for (int b = 0; b < 4; b++)
            #pragma unroll
            for (int c = 0; c < 4; c++) acc[a][b][c] = 0.f;

    auto cpB = [&](int s, int kt) {
        uint32_t st = smbase + s * STAGE_B + TILE_B;
        const int kof = kt * 64;
        #pragma unroll
        for (int i = 0; i < 4; i++) {
            int q = tid + i * 256;
            int r = q >> 3, ch = q & 7;
            cp16(st + r * ROWB + ch * 16, Bh + (size_t)(bn + r) * GK + kof + ch * 8);
        }
    };

    auto compute = [&](int s) {
        uint32_t st = smbase + s * STAGE_B;
        #pragma unroll
        for (int ks = 0; ks < 4; ks++) {
            const int kof = ks * 16;
            uint32_t ah[4][4];
            #pragma unroll
            for (int mi = 0; mi < 4; mi++) {
                uint32_t addr = st + (wm + mi * 16 + (lane & 15)) * ROWB
                              + (kof + (lane >> 4) * 8) * 2;
                ldsm4(ah[mi], addr);
            }
            #pragma unroll
            for (int nip = 0; nip < 2; nip++) {
                uint32_t baddr = st + TILE_B
                               + (wn + nip * 16 + (lane & 7) + ((lane >> 4) << 3)) * ROWB
                               + (kof + ((lane >> 3) & 1) * 8) * 2;
                uint32_t bh[4];
                ldsm4(bh, baddr);
                #pragma unroll
                for (int mi = 0; mi < 4; mi++) {
                    mma16816(acc[mi][2 * nip],     ah[mi], bh[0], bh[1]);
                    mma16816(acc[mi][2 * nip + 1], ah[mi], bh[2], bh[3]);
                }
            }
        }
    };

    if (Afp32) {
        // ---- fp32 A: LDG kt+2 before compute, cvt+STS after; B via cp.async ----
        float4 areg[8];
        auto ldgA = [&](int kt) {
            const int kof = kt * 64;
            #pragma unroll
            for (int i = 0; i < 8; i++) {
                int q = tid + i * 256;
                int r = q >> 4, ch = q & 15;
                areg[i] = *reinterpret_cast<const float4*>(
                    Afp32 + (size_t)(bm + r) * GK + kof + ch * 4);
            }
        };
        auto stsA = [&](int s) {
            uint32_t st = smbase + s * STAGE_B;
            #pragma unroll
            for (int i = 0; i < 8; i++) {
                int q = tid + i * 256;
                int r = q >> 4, ch = q & 15;
                __half2 h01 = __floats2half2_rn(areg[i].x, areg[i].y);
                __half2 h23 = __floats2half2_rn(areg[i].z, areg[i].w);
                asm volatile("st.shared.v2.b32 [%0], {%1,%2};"
                             :: "r"(st + r * ROWB + ch * 8), "r"(h2u(h01)), "r"(h2u(h23)));
            }
        };

        ldgA(0); stsA(0);
        ldgA(1); stsA(1);
        cpB(0, 0);
        asm volatile("cp.async.commit_group;" ::: "memory");
        cpB(1, 1);
        asm volatile("cp.async.commit_group;" ::: "memory");

        for (int kt = 0; kt < NKT; kt++) {
            if (kt < NKT - 1) asm volatile("cp.async.wait_group 1;" ::: "memory");
            else              asm volatile("cp.async.wait_group 0;" ::: "memory");
            __syncthreads();
            if (kt + 2 < NKT) {
                ldgA(kt + 2);
                cpB((kt + 2) % 3, kt + 2);
                asm volatile("cp.async.commit_group;" ::: "memory");
            }
            compute(kt % 3);
            if (kt + 2 < NKT) stsA((kt + 2) % 3);
        }
    } else {
        // ---- fp16 A from g_Xh: both tiles via cp.async, 3-stage ring ----
        auto cpA = [&](int s, int kt) {
            uint32_t st = smbase + s * STAGE_B;
            const int kof = kt * 64;
            #pragma unroll
            for (int i = 0; i < 4; i++) {
                int q = tid + i * 256;
                int r = q >> 3, ch = q & 7;
                cp16(st + r * ROWB + ch * 16, g_Xh + (size_t)(bm + r) * GK + kof + ch * 8);
            }
        };
        cpA(0, 0); cpB(0, 0);
        asm volatile("cp.async.commit_group;" ::: "memory");
        cpA(1, 1); cpB(1, 1);
        asm volatile("cp.async.commit_group;" ::: "memory");

        for (int kt = 0; kt < NKT; kt++) {
            if (kt < NKT - 1) asm volatile("cp.async.wait_group 1;" ::: "memory");
            else              asm volatile("cp.async.wait_group 0;" ::: "memory");
            __syncthreads();
            if (kt + 2 < NKT) {
                cpA((kt + 2) % 3, kt + 2);
                cpB((kt + 2) % 3, kt + 2);
                asm volatile("cp.async.commit_group;" ::: "memory");
            }
            compute(kt % 3);
        }
    }

    __half* Ch = half_out_ptr(c_tag);
    #pragma unroll
    for (int mi = 0; mi < 4; mi++) {
        int row = bm + wm + mi * 16 + gid;
        #pragma unroll
        for (int ni = 0; ni < 4; ni++) {
            int col = bn + wn + ni * 8 + tig * 2;
            float b0 = bias[col], b1 = bias[col + 1];
            float v0 = acc[mi][ni][0] + b0, v1 = acc[mi][ni][1] + b1;
            float v2 = acc[mi][ni][2] + b0, v3 = acc[mi][ni][3] + b1;
            if (Ch) {
                __half2 p01 = __floats2half2_rn(v0, v1);
                __half2 p23 = __floats2half2_rn(v2, v3);
                *reinterpret_cast<uint32_t*>(&Ch[(size_t)row * GN + col])       = h2u(p01);
                *reinterpret_cast<uint32_t*>(&Ch[(size_t)(row + 8) * GN + col]) = h2u(p23);
            } else {
                *reinterpret_cast<float2*>(&Cout[(size_t)row * GN + col])       = make_float2(v0, v1);
                *reinterpret_cast<float2*>(&Cout[(size_t)(row + 8) * GN + col]) = make_float2(v2, v3);
            }
        }
    }
}

// ---------------------------------------------------------------------------
// Attention, warp-per-position, tensor cores. V kept ROW-MAJOR in smem;
// AV B-fragments loaded via ldmatrix.trans (no software transpose).
// Per-warp smem: Qs/Ks/Vs 16x144B each + qn/kn floats = 7040 B.
// ---------------------------------------------------------------------------
#define AW_QS   0
#define AW_KS   2304
#define AW_VS   4608
#define AW_QN   6912
#define AW_KN   6976
#define AW_SZ   7040
#define ASMEM   (8 * AW_SZ)   // 56320

__global__ __launch_bounds__(256) void attn_kernel(
    const float* __restrict__ SW, float* AT)
{
    extern __shared__ __align__(16) char dynsm[];
    const int warp = threadIdx.x >> 5;
    const int lane = threadIdx.x & 31;
    const int p = blockIdx.x * 8 + warp;
    const int b = p >> 12;
    const int s = p & 4095;

    char* wsm = dynsm + warp * AW_SZ;
    const uint32_t wsb = (uint32_t)__cvta_generic_to_shared(dynsm) + warp * AW_SZ;
    const size_t base = (size_t)p * 1024;

    float w0, w1, w2;
    {
        float s0 = SW[0], s1 = SW[1], s2 = SW[2];
        float mx = fmaxf(s0, fmaxf(s1, s2));
        float e0 = expf(s0 - mx), e1 = expf(s1 - mx), e2 = expf(s2 - mx);
        float inv = 1.f / (e0 + e1 + e2);
        w0 = e0 * inv; w1 = e1 * inv; w2 = e2 * inv;
    }

    // ---- load Q,K (fused norms) and V, all row-major (144B rows) ----
    {
        const int rw = lane >> 1, hp = lane & 1;
        const size_t go = base + (size_t)rw * 64 + hp * 32;

        uint4 q0 = *reinterpret_cast<const uint4*>(g_Qh + go);
        uint4 q1 = *reinterpret_cast<const uint4*>(g_Qh + go + 8);
        uint4 q2 = *reinterpret_cast<const uint4*>(g_Qh + go + 16);
        uint4 q3 = *reinterpret_cast<const uint4*>(g_Qh + go + 24);
        uint4* qdst = reinterpret_cast<uint4*>(wsm + AW_QS + rw * 144 + hp * 64);
        qdst[0] = q0; qdst[1] = q1; qdst[2] = q2; qdst[3] = q3;
        float qsum = sumsq16(q0) + sumsq16(q1) + sumsq16(q2) + sumsq16(q3);
        qsum += __shfl_xor_sync(0xffffffffu, qsum, 1);
        if (hp == 0) reinterpret_cast<float*>(wsm + AW_QN)[rw] = qsum;

        uint4 k0 = *reinterpret_cast<const uint4*>(g_Kh + go);
        uint4 k1 = *reinterpret_cast<const uint4*>(g_Kh + go + 8);
        uint4 k2 = *reinterpret_cast<const uint4*>(g_Kh + go + 16);
        uint4 k3 = *reinterpret_cast<const uint4*>(g_Kh + go + 24);
        uint4* kdst = reinterpret_cast<uint4*>(wsm + AW_KS + rw * 144 + hp * 64);
        kdst[0] = k0; kdst[1] = k1; kdst[2] = k2; kdst[3] = k3;
        float ksum = sumsq16(k0) + sumsq16(k1) + sumsq16(k2) + sumsq16(k3);
        ksum += __shfl_xor_sync(0xffffffffu, ksum, 1);
        if (hp == 0) reinterpret_cast<float*>(wsm + AW_KN)[rw] = ksum;

        uint4 v0 = *reinterpret_cast<const uint4*>(g_Vh + go);
        uint4 v1 = *reinterpret_cast<const uint4*>(g_Vh + go + 8);
        uint4 v2 = *reinterpret_cast<const uint4*>(g_Vh + go + 16);
        uint4 v3 = *reinterpret_cast<const uint4*>(g_Vh + go + 24);
        uint4* vdst = reinterpret_cast<uint4*>(wsm + AW_VS + rw * 144 + hp * 64);
        vdst[0] = v0; vdst[1] = v1; vdst[2] = v2; vdst[3] = v3;
    }
    __syncwarp();

    // ---- scores: 4 k-steps x 2 n-tiles of MMA ----
    float c0[4] = {0.f, 0.f, 0.f, 0.f};
    float c1[4] = {0.f, 0.f, 0.f, 0.f};
    #pragma unroll
    for (int kk = 0; kk < 4; kk++) {
        uint32_t a[4];
        ldsm4(a, wsb + AW_QS + (lane & 15) * 144 + (kk * 16 + (lane >> 4) * 8) * 2);
        uint32_t bb[4];
        ldsm4(bb, wsb + AW_KS + ((lane & 7) + ((lane >> 4) << 3)) * 144
                      + (kk * 16 + ((lane >> 3) & 1) * 8) * 2);
        mma16816(c0, a, bb[0], bb[1]);
        mma16816(c1, a, bb[2], bb[3]);
    }

    // ---- score transform + softmax (rows r and r+8 per lane) ----
    const int r = lane >> 2, tg = lane & 3;
    const float* qnp = reinterpret_cast<const float*>(wsm + AW_QN);
    const float* knp = reinterpret_cast<const float*>(wsm + AW_KN);
    float qq0 = qnp[r], qq8 = qnp[r + 8];
    float kn0 = knp[2 * tg], kn1 = knp[2 * tg + 1];
    float kn8 = knp[2 * tg + 8], kn9 = knp[2 * tg + 9];

    auto scf = [&](float qk, float qq, float kk) {
        float dots  = qk * 0.125f;
        float denom = fmaxf(sqrtf(qq) * sqrtf(kk), 1e-8f);
        float cosv  = qk / denom;
        float d2    = fmaxf(qq + kk - 2.f * qk, 0.f);
        return w0 * dots + w1 * cosv + w2 * (-sqrtf(d2));
    };

    float A = scf(c0[0], qq0, kn0), B = scf(c0[1], qq0, kn1);
    float C = scf(c0[2], qq8, kn0), D = scf(c0[3], qq8, kn1);
    float E = scf(c1[0], qq0, kn8), F = scf(c1[1], qq0, kn9);
    float G = scf(c1[2], qq8, kn8), H = scf(c1[3], qq8, kn9);

    float m0 = fmaxf(fmaxf(A, B), fmaxf(E, F));
    float m1 = fmaxf(fmaxf(C, D), fmaxf(G, H));
    m0 = fmaxf(m0, __shfl_xor_sync(0xffffffffu, m0, 1));
    m0 = fmaxf(m0, __shfl_xor_sync(0xffffffffu, m0, 2));
    m1 = fmaxf(m1, __shfl_xor_sync(0xffffffffu, m1, 1));
    m1 = fmaxf(m1, __shfl_xor_sync(0xffffffffu, m1, 2));

    float eA = expf(A - m0), eB = expf(B - m0), eE = expf(E - m0), eF = expf(F - m0);
    float eC = expf(C - m1), eD = expf(D - m1), eG = expf(G - m1), eH = expf(H - m1);
    float s0 = eA + eB + eE + eF;
    float s1 = eC + eD + eG + eH;
    s0 += __shfl_xor_sync(0xffffffffu, s0, 1);
    s0 += __shfl_xor_sync(0xffffffffu, s0, 2);
    s1 += __shfl_xor_sync(0xffffffffu, s1, 1);
    s1 += __shfl_xor_sync(0xffffffffu, s1, 2);
    float i0 = 1.f / s0, i1 = 1.f / s1;
    float aA = eA * i0, aB = eB * i0, aE = eE * i0, aF = eF * i0;
    float aC = eC * i1, aD = eD * i1, aG = eG * i1, aH = eH * i1;

    if (AT) {
        size_t pb = (size_t)p * 256;
        *reinterpret_cast<float2*>(&AT[pb + r * 16 + 2 * tg])           = make_float2(aA, aB);
        *reinterpret_cast<float2*>(&AT[pb + r * 16 + 8 + 2 * tg])       = make_float2(aE, aF);
        *reinterpret_cast<float2*>(&AT[pb + (r + 8) * 16 + 2 * tg])     = make_float2(aC, aD);
        *reinterpret_cast<float2*>(&AT[pb + (r + 8) * 16 + 8 + 2 * tg]) = make_float2(aG, aH);
    }

    // ---- AV: att accumulator layout == A fragment layout; V via trans ldsm ----
    uint32_t af[4];
    af[0] = h2u(__floats2half2_rn(aA, aB));
    af[1] = h2u(__floats2half2_rn(aC, aD));
    af[2] = h2u(__floats2half2_rn(aE, aF));
    af[3] = h2u(__floats2half2_rn(aG, aH));

    float o[8][4];
    #pragma unroll
    for (int i = 0; i < 8; i++)
        #pragma unroll
        for (int j = 0; j < 4; j++) o[i][j] = 0.f;

    #pragma unroll
    for (int t2 = 0; t2 < 4; t2++) {
        uint32_t bb[4];
        ldsm4t(bb, wsb + AW_VS + (lane & 15) * 144 + (t2 * 16 + (lane >> 4) * 8) * 2);
        mma16816(o[2 * t2],     af, bb[0], bb[1]);
        mma16816(o[2 * t2 + 1], af, bb[2], bb[3]);
    }

    // ---- store X fp16 (B,H,S,D): head = score row, d = AV col ----
    {
        size_t xb = (size_t)b * 4194304 + (size_t)s * 64;
        #pragma unroll
        for (int nt = 0; nt < 8; nt++) {
            int d0 = nt * 8 + 2 * tg;
            *reinterpret_cast<uint32_t*>(&g_Xh[xb + (size_t)r * 262144 + d0]) =
                h2u(__floats2half2_rn(o[nt][0], o[nt][1]));
            *reinterpret_cast<uint32_t*>(&g_Xh[xb + (size_t)(r + 8) * 262144 + d0]) =
                h2u(__floats2half2_rn(o[nt][2], o[nt][3]));
        }
    }
}

// ---------------------------------------------------------------------------
// kernel_launch
// ---------------------------------------------------------------------------
extern "C" void kernel_launch(void* const* d_in, const int* in_sizes, int n_in,
                              void* d_out, int out_size) {
    (void)in_sizes; (void)n_in;
    const float* query = (const float*)d_in[0];
    const float* key   = (const float*)d_in[1];
    const float* value = (const float*)d_in[2];
    const float* Wq = (const float*)d_in[3];
    const float* bq = (const float*)d_in[4];
    const float* Wk = (const float*)d_in[5];
    const float* bk = (const float*)d_in[6];
    const float* Wv = (const float*)d_in[7];
    const float* bv = (const float*)d_in[8];
    const float* Wo = (const float*)d_in[9];
    const float* bo = (const float*)d_in[10];
    const float* sw = (const float*)d_in[11];
    float* out = (float*)d_out;

    static bool attr_set = false;
    if (!attr_set) {
        cudaFuncSetAttribute(gemm_tc_kernel,
                             cudaFuncAttributeMaxDynamicSharedMemorySize, GSMEM);
        cudaFuncSetAttribute(attn_kernel,
                             cudaFuncAttributeMaxDynamicSharedMemorySize, ASMEM);
        attr_set = true;
    }

    dim3 ggrid(GN / 128, GM / 128);   // (8, 128)
    dim3 swgrid(GN / 32, GK / 32, 4); // (32, 32, 4)

    // 1: W^T splits
    split_wt4_kernel<<<swgrid, 256>>>(Wq, Wk, Wv, Wo);

    // 2,3,4: Q, K, V projections (fp32 A inline-converted; fp16 C)
    gemm_tc_kernel<<<ggrid, 256, GSMEM>>>(query, 0, nullptr, 1, bq);
    gemm_tc_kernel<<<ggrid, 256, GSMEM>>>(key,   1, nullptr, 2, bk);
    gemm_tc_kernel<<<ggrid, 256, GSMEM>>>(value, 2, nullptr, 3, bv);

    // 5: attention (warp per position; 8 positions per CTA)
    float* attn_dst = (out_size >= MAIN_OUT_ELEMS + ATT_ELEMS) ? (out + MAIN_OUT_ELEMS)
                                                               : nullptr;
    attn_kernel<<<NPOS / 8, 256, ASMEM>>>(sw, attn_dst);

    // 6: output projection (fp16 A from g_Xh; fp32 C = d_out)
    gemm_tc_kernel<<<ggrid, 256, GSMEM>>>(nullptr, 3, out, 0, bo);
}

// round 17
// speedup vs baseline: 1.0378x; 1.0378x over previous
#include <cuda_runtime.h>
#include <cuda_fp16.h>
#include <stdint.h>

// Problem constants (B=4, S=4096, HID=1024, H=16, D=64)
#define GM 16384
#define GN 1024
#define GK 1024
#define NPOS 16384
#define ATT_ELEMS (NPOS * 256)
#define MAIN_OUT_ELEMS (GM * GN)
#define WSLOT ((size_t)GN * GK)

// Device-global scratch (no allocations allowed)
__device__ __align__(16) __half g_Qh[(size_t)GM * GN];
__device__ __align__(16) __half g_Kh[(size_t)GM * GN];
__device__ __align__(16) __half g_Vh[(size_t)GM * GN];
__device__ __align__(16) __half g_Xh[(size_t)GM * GK];   // (B,H,S,D) fp16
__device__ __align__(16) __half g_Wth[4 * WSLOT];        // W^T fp16, slots 0..3

// ---------------------------------------------------------------------------
// helpers
// ---------------------------------------------------------------------------
__device__ __forceinline__ void mma16816(float* c, const uint32_t* a, uint32_t b0, uint32_t b1) {
    asm volatile(
        "mma.sync.aligned.m16n8k16.row.col.f32.f16.f16.f32 "
        "{%0,%1,%2,%3}, {%4,%5,%6,%7}, {%8,%9}, {%0,%1,%2,%3};"
        : "+f"(c[0]), "+f"(c[1]), "+f"(c[2]), "+f"(c[3])
        : "r"(a[0]), "r"(a[1]), "r"(a[2]), "r"(a[3]), "r"(b0), "r"(b1));
}

__device__ __forceinline__ void ldsm4(uint32_t* r, uint32_t addr) {
    asm volatile("ldmatrix.sync.aligned.m8n8.x4.shared.b16 {%0,%1,%2,%3}, [%4];"
                 : "=r"(r[0]), "=r"(r[1]), "=r"(r[2]), "=r"(r[3]) : "r"(addr));
}

__device__ __forceinline__ void ldsm4t(uint32_t* r, uint32_t addr) {
    asm volatile("ldmatrix.sync.aligned.m8n8.x4.trans.shared.b16 {%0,%1,%2,%3}, [%4];"
                 : "=r"(r[0]), "=r"(r[1]), "=r"(r[2]), "=r"(r[3]) : "r"(addr));
}

__device__ __forceinline__ void cp16(uint32_t dst, const void* src) {
    asm volatile("cp.async.cg.shared.global [%0], [%1], 16;" :: "r"(dst), "l"(src));
}

__device__ __forceinline__ uint32_t h2u(__half2 h) { return *reinterpret_cast<uint32_t*>(&h); }

__device__ __forceinline__ float sumsq16(uint4 u) {
    const __half2* h = reinterpret_cast<const __half2*>(&u);
    float s = 0.f;
    #pragma unroll
    for (int i = 0; i < 4; i++) {
        float2 f = __half22float2(h[i]);
        s += f.x * f.x + f.y * f.y;
    }
    return s;
}

// ---------------------------------------------------------------------------
// W split: fp32 [K,N] -> fp16 [N,K] (transpose). blockIdx.z selects W.
// ---------------------------------------------------------------------------
__global__ __launch_bounds__(256) void split_wt4_kernel(
    const float* __restrict__ w0, const float* __restrict__ w1,
    const float* __restrict__ w2, const float* __restrict__ w3)
{
    const int z = blockIdx.z;
    const float* W = (z == 0) ? w0 : (z == 1) ? w1 : (z == 2) ? w2 : w3;
    __half* Wh = g_Wth + (size_t)z * WSLOT;

    __shared__ float t[32][33];
    int n0 = blockIdx.x * 32, k0 = blockIdx.y * 32;
    int tx = threadIdx.x & 31, ty = threadIdx.x >> 5;
    #pragma unroll
    for (int j = 0; j < 4; j++)
        t[ty + 8 * j][tx] = W[(size_t)(k0 + ty + 8 * j) * GN + n0 + tx];
    __syncthreads();
    #pragma unroll
    for (int j = 0; j < 4; j++) {
        int r = ty + 8 * j;
        Wh[(size_t)(n0 + r) * GK + k0 + tx] = __float2half_rn(t[tx][r]);
    }
}

// ---------------------------------------------------------------------------
// GEMM (R14/R15 2-stage version — measured fastest): C = A @ W + bias.
// fp16 MMA, fp32 accum. CTA 128x128, BK=64, 8 warps (2x4), warp 64x32.
// ---------------------------------------------------------------------------
#define ROWB     144
#define TILE_B   (128 * ROWB)
#define STAGE_B  (2 * TILE_B)
#define GSMEM    (2 * STAGE_B)       // 73728
#define NKT      16

__device__ __forceinline__ __half* half_out_ptr(int tag) {
    switch (tag) { case 1: return g_Qh; case 2: return g_Kh;
                   case 3: return g_Vh; default: return nullptr; }
}

__global__ __launch_bounds__(256, 1) void gemm_tc_kernel(
    const float* __restrict__ Afp32, int w_slot,
    float* Cout, int c_tag, const float* __restrict__ bias)
{
    const __half* Bh = g_Wth + (size_t)w_slot * WSLOT;

    extern __shared__ __align__(16) char sm[];
    const uint32_t smbase = (uint32_t)__cvta_generic_to_shared(sm);

    const int tid  = threadIdx.x;
    const int warp = tid >> 5;
    const int lane = tid & 31;
    const int gid  = lane >> 2;
    const int tig  = lane & 3;
    const int wm = (warp >> 2) * 64;
    const int wn = (warp & 3) * 32;
    const int bm = blockIdx.y * 128;
    const int bn = blockIdx.x * 128;

    float acc[4][4][4];
    #pragma unroll
    for (int a = 0; a < 4; a++)
        #pragma unroll
        for (int b = 0; b < 4; b++)
            #pragma unroll
            for (int c = 0; c < 4; c++) acc[a][b][c] = 0.f;

    auto cpB = [&](int s, int kt) {
        uint32_t st = smbase + s * STAGE_B + TILE_B;
        const int kof = kt * 64;
        #pragma unroll
        for (int i = 0; i < 4; i++) {
            int q = tid + i * 256;
            int r = q >> 3, ch = q & 7;
            cp16(st + r * ROWB + ch * 16, Bh + (size_t)(bn + r) * GK + kof + ch * 8);
        }
        asm volatile("cp.async.commit_group;" ::: "memory");
    };

    auto compute = [&](int s) {
        uint32_t st = smbase + s * STAGE_B;
        #pragma unroll
        for (int ks = 0; ks < 4; ks++) {
            const int kof = ks * 16;
            uint32_t ah[4][4];
            #pragma unroll
            for (int mi = 0; mi < 4; mi++) {
                uint32_t addr = st + (wm + mi * 16 + (lane & 15)) * ROWB
                              + (kof + (lane >> 4) * 8) * 2;
                ldsm4(ah[mi], addr);
            }
            #pragma unroll
            for (int nip = 0; nip < 2; nip++) {
                uint32_t baddr = st + TILE_B
                               + (wn + nip * 16 + (lane & 7) + ((lane >> 4) << 3)) * ROWB
                               + (kof + ((lane >> 3) & 1) * 8) * 2;
                uint32_t bh[4];
                ldsm4(bh, baddr);
                #pragma unroll
                for (int mi = 0; mi < 4; mi++) {
                    mma16816(acc[mi][2 * nip],     ah[mi], bh[0], bh[1]);
                    mma16816(acc[mi][2 * nip + 1], ah[mi], bh[2], bh[3]);
                }
            }
        }
    };

    if (Afp32) {
        float4 areg[8];
        auto ldgA = [&](int kt) {
            const int kof = kt * 64;
            #pragma unroll
            for (int i = 0; i < 8; i++) {
                int q = tid + i * 256;
                int r = q >> 4, ch = q & 15;
                areg[i] = *reinterpret_cast<const float4*>(
                    Afp32 + (size_t)(bm + r) * GK + kof + ch * 4);
            }
        };
        auto stsA = [&](int s) {
            uint32_t st = smbase + s * STAGE_B;
            #pragma unroll
            for (int i = 0; i < 8; i++) {
                int q = tid + i * 256;
                int r = q >> 4, ch = q & 15;
                __half2 h01 = __floats2half2_rn(areg[i].x, areg[i].y);
                __half2 h23 = __floats2half2_rn(areg[i].z, areg[i].w);
                asm volatile("st.shared.v2.b32 [%0], {%1,%2};"
                             :: "r"(st + r * ROWB + ch * 8), "r"(h2u(h01)), "r"(h2u(h23)));
            }
        };

        ldgA(0); cpB(0, 0);
        stsA(0);
        for (int kt = 0; kt < NKT; kt++) {
            asm volatile("cp.async.wait_group 0;" ::: "memory");
            __syncthreads();
            if (kt + 1 < NKT) { ldgA(kt + 1); cpB((kt + 1) & 1, kt + 1); }
            compute(kt & 1);
            if (kt + 1 < NKT) stsA((kt + 1) & 1);
        }
    } else {
        auto cpA = [&](int s, int kt) {
            uint32_t st = smbase + s * STAGE_B;
            const int kof = kt * 64;
            #pragma unroll
            for (int i = 0; i < 4; i++) {
                int q = tid + i * 256;
                int r = q >> 3, ch = q & 7;
                cp16(st + r * ROWB + ch * 16, g_Xh + (size_t)(bm + r) * GK + kof + ch * 8);
            }
        };
        cpA(0, 0); cpB(0, 0);
        for (int kt = 0; kt < NKT; kt++) {
            asm volatile("cp.async.wait_group 0;" ::: "memory");
            __syncthreads();
            if (kt + 1 < NKT) { cpA((kt + 1) & 1, kt + 1); cpB((kt + 1) & 1, kt + 1); }
            compute(kt & 1);
        }
    }

    __half* Ch = half_out_ptr(c_tag);
    #pragma unroll
    for (int mi = 0; mi < 4; mi++) {
        int row = bm + wm + mi * 16 + gid;
        #pragma unroll
        for (int ni = 0; ni < 4; ni++) {
            int col = bn + wn + ni * 8 + tig * 2;
            float b0 = bias[col], b1 = bias[col + 1];
            float v0 = acc[mi][ni][0] + b0, v1 = acc[mi][ni][1] + b1;
            float v2 = acc[mi][ni][2] + b0, v3 = acc[mi][ni][3] + b1;
            if (Ch) {
                __half2 p01 = __floats2half2_rn(v0, v1);
                __half2 p23 = __floats2half2_rn(v2, v3);
                *reinterpret_cast<uint32_t*>(&Ch[(size_t)row * GN + col])       = h2u(p01);
                *reinterpret_cast<uint32_t*>(&Ch[(size_t)(row + 8) * GN + col]) = h2u(p23);
            } else {
                *reinterpret_cast<float2*>(&Cout[(size_t)row * GN + col])       = make_float2(v0, v1);
                *reinterpret_cast<float2*>(&Cout[(size_t)(row + 8) * GN + col]) = make_float2(v2, v3);
            }
        }
    }
}

// ---------------------------------------------------------------------------
// Attention (R16 version — verified bit-identical): warp-per-position,
// tensor cores, V row-major with ldmatrix.trans AV fragments.
// ---------------------------------------------------------------------------
#define AW_QS   0
#define AW_KS   2304
#define AW_VS   4608
#define AW_QN   6912
#define AW_KN   6976
#define AW_SZ   7040
#define ASMEM   (8 * AW_SZ)   // 56320

__global__ __launch_bounds__(256) void attn_kernel(
    const float* __restrict__ SW, float* AT)
{
    extern __shared__ __align__(16) char dynsm[];
    const int warp = threadIdx.x >> 5;
    const int lane = threadIdx.x & 31;
    const int p = blockIdx.x * 8 + warp;
    const int b = p >> 12;
    const int s = p & 4095;

    char* wsm = dynsm + warp * AW_SZ;
    const uint32_t wsb = (uint32_t)__cvta_generic_to_shared(dynsm) + warp * AW_SZ;
    const size_t base = (size_t)p * 1024;

    float w0, w1, w2;
    {
        float s0 = SW[0], s1 = SW[1], s2 = SW[2];
        float mx = fmaxf(s0, fmaxf(s1, s2));
        float e0 = expf(s0 - mx), e1 = expf(s1 - mx), e2 = expf(s2 - mx);
        float inv = 1.f / (e0 + e1 + e2);
        w0 = e0 * inv; w1 = e1 * inv; w2 = e2 * inv;
    }

    // ---- load Q,K (fused norms) and V, all row-major (144B rows) ----
    {
        const int rw = lane >> 1, hp = lane & 1;
        const size_t go = base + (size_t)rw * 64 + hp * 32;

        uint4 q0 = *reinterpret_cast<const uint4*>(g_Qh + go);
        uint4 q1 = *reinterpret_cast<const uint4*>(g_Qh + go + 8);
        uint4 q2 = *reinterpret_cast<const uint4*>(g_Qh + go + 16);
        uint4 q3 = *reinterpret_cast<const uint4*>(g_Qh + go + 24);
        uint4* qdst = reinterpret_cast<uint4*>(wsm + AW_QS + rw * 144 + hp * 64);
        qdst[0] = q0; qdst[1] = q1; qdst[2] = q2; qdst[3] = q3;
        float qsum = sumsq16(q0) + sumsq16(q1) + sumsq16(q2) + sumsq16(q3);
        qsum += __shfl_xor_sync(0xffffffffu, qsum, 1);
        if (hp == 0) reinterpret_cast<float*>(wsm + AW_QN)[rw] = qsum;

        uint4 k0 = *reinterpret_cast<const uint4*>(g_Kh + go);
        uint4 k1 = *reinterpret_cast<const uint4*>(g_Kh + go + 8);
        uint4 k2 = *reinterpret_cast<const uint4*>(g_Kh + go + 16);
        uint4 k3 = *reinterpret_cast<const uint4*>(g_Kh + go + 24);
        uint4* kdst = reinterpret_cast<uint4*>(wsm + AW_KS + rw * 144 + hp * 64);
        kdst[0] = k0; kdst[1] = k1; kdst[2] = k2; kdst[3] = k3;
        float ksum = sumsq16(k0) + sumsq16(k1) + sumsq16(k2) + sumsq16(k3);
        ksum += __shfl_xor_sync(0xffffffffu, ksum, 1);
        if (hp == 0) reinterpret_cast<float*>(wsm + AW_KN)[rw] = ksum;

        uint4 v0 = *reinterpret_cast<const uint4*>(g_Vh + go);
        uint4 v1 = *reinterpret_cast<const uint4*>(g_Vh + go + 8);
        uint4 v2 = *reinterpret_cast<const uint4*>(g_Vh + go + 16);
        uint4 v3 = *reinterpret_cast<const uint4*>(g_Vh + go + 24);
        uint4* vdst = reinterpret_cast<uint4*>(wsm + AW_VS + rw * 144 + hp * 64);
        vdst[0] = v0; vdst[1] = v1; vdst[2] = v2; vdst[3] = v3;
    }
    __syncwarp();

    // ---- scores: 4 k-steps x 2 n-tiles of MMA ----
    float c0[4] = {0.f, 0.f, 0.f, 0.f};
    float c1[4] = {0.f, 0.f, 0.f, 0.f};
    #pragma unroll
    for (int kk = 0; kk < 4; kk++) {
        uint32_t a[4];
        ldsm4(a, wsb + AW_QS + (lane & 15) * 144 + (kk * 16 + (lane >> 4) * 8) * 2);
        uint32_t bb[4];
        ldsm4(bb, wsb + AW_KS + ((lane & 7) + ((lane >> 4) << 3)) * 144
                      + (kk * 16 + ((lane >> 3) & 1) * 8) * 2);
        mma16816(c0, a, bb[0], bb[1]);
        mma16816(c1, a, bb[2], bb[3]);
    }

    // ---- score transform + softmax (rows r and r+8 per lane) ----
    const int r = lane >> 2, tg = lane & 3;
    const float* qnp = reinterpret_cast<const float*>(wsm + AW_QN);
    const float* knp = reinterpret_cast<const float*>(wsm + AW_KN);
    float qq0 = qnp[r], qq8 = qnp[r + 8];
    float kn0 = knp[2 * tg], kn1 = knp[2 * tg + 1];
    float kn8 = knp[2 * tg + 8], kn9 = knp[2 * tg + 9];

    auto scf = [&](float qk, float qq, float kk) {
        float dots  = qk * 0.125f;
        float denom = fmaxf(sqrtf(qq) * sqrtf(kk), 1e-8f);
        float cosv  = qk / denom;
        float d2    = fmaxf(qq + kk - 2.f * qk, 0.f);
        return w0 * dots + w1 * cosv + w2 * (-sqrtf(d2));
    };

    float A = scf(c0[0], qq0, kn0), B = scf(c0[1], qq0, kn1);
    float C = scf(c0[2], qq8, kn0), D = scf(c0[3], qq8, kn1);
    float E = scf(c1[0], qq0, kn8), F = scf(c1[1], qq0, kn9);
    float G = scf(c1[2], qq8, kn8), H = scf(c1[3], qq8, kn9);

    float m0 = fmaxf(fmaxf(A, B), fmaxf(E, F));
    float m1 = fmaxf(fmaxf(C, D), fmaxf(G, H));
    m0 = fmaxf(m0, __shfl_xor_sync(0xffffffffu, m0, 1));
    m0 = fmaxf(m0, __shfl_xor_sync(0xffffffffu, m0, 2));
    m1 = fmaxf(m1, __shfl_xor_sync(0xffffffffu, m1, 1));
    m1 = fmaxf(m1, __shfl_xor_sync(0xffffffffu, m1, 2));

    float eA = expf(A - m0), eB = expf(B - m0), eE = expf(E - m0), eF = expf(F - m0);
    float eC = expf(C - m1), eD = expf(D - m1), eG = expf(G - m1), eH = expf(H - m1);
    float s0 = eA + eB + eE + eF;
    float s1 = eC + eD + eG + eH;
    s0 += __shfl_xor_sync(0xffffffffu, s0, 1);
    s0 += __shfl_xor_sync(0xffffffffu, s0, 2);
    s1 += __shfl_xor_sync(0xffffffffu, s1, 1);
    s1 += __shfl_xor_sync(0xffffffffu, s1, 2);
    float i0 = 1.f / s0, i1 = 1.f / s1;
    float aA = eA * i0, aB = eB * i0, aE = eE * i0, aF = eF * i0;
    float aC = eC * i1, aD = eD * i1, aG = eG * i1, aH = eH * i1;

    if (AT) {
        size_t pb = (size_t)p * 256;
        *reinterpret_cast<float2*>(&AT[pb + r * 16 + 2 * tg])           = make_float2(aA, aB);
        *reinterpret_cast<float2*>(&AT[pb + r * 16 + 8 + 2 * tg])       = make_float2(aE, aF);
        *reinterpret_cast<float2*>(&AT[pb + (r + 8) * 16 + 2 * tg])     = make_float2(aC, aD);
        *reinterpret_cast<float2*>(&AT[pb + (r + 8) * 16 + 8 + 2 * tg]) = make_float2(aG, aH);
    }

    // ---- AV: att accumulator layout == A fragment layout; V via trans ldsm ----
    uint32_t af[4];
    af[0] = h2u(__floats2half2_rn(aA, aB));
    af[1] = h2u(__floats2half2_rn(aC, aD));
    af[2] = h2u(__floats2half2_rn(aE, aF));
    af[3] = h2u(__floats2half2_rn(aG, aH));

    float o[8][4];
    #pragma unroll
    for (int i = 0; i < 8; i++)
        #pragma unroll
        for (int j = 0; j < 4; j++) o[i][j] = 0.f;

    #pragma unroll
    for (int t2 = 0; t2 < 4; t2++) {
        uint32_t bb[4];
        ldsm4t(bb, wsb + AW_VS + (lane & 15) * 144 + (t2 * 16 + (lane >> 4) * 8) * 2);
        mma16816(o[2 * t2],     af, bb[0], bb[1]);
        mma16816(o[2 * t2 + 1], af, bb[2], bb[3]);
    }

    // ---- store X fp16 (B,H,S,D): head = score row, d = AV col ----
    {
        size_t xb = (size_t)b * 4194304 + (size_t)s * 64;
        #pragma unroll
        for (int nt = 0; nt < 8; nt++) {
            int d0 = nt * 8 + 2 * tg;
            *reinterpret_cast<uint32_t*>(&g_Xh[xb + (size_t)r * 262144 + d0]) =
                h2u(__floats2half2_rn(o[nt][0], o[nt][1]));
            *reinterpret_cast<uint32_t*>(&g_Xh[xb + (size_t)(r + 8) * 262144 + d0]) =
                h2u(__floats2half2_rn(o[nt][2], o[nt][3]));
        }
    }
}

// ---------------------------------------------------------------------------
// kernel_launch
// ---------------------------------------------------------------------------
extern "C" void kernel_launch(void* const* d_in, const int* in_sizes, int n_in,
                              void* d_out, int out_size) {
    (void)in_sizes; (void)n_in;
    const float* query = (const float*)d_in[0];
    const float* key   = (const float*)d_in[1];
    const float* value = (const float*)d_in[2];
    const float* Wq = (const float*)d_in[3];
    const float* bq = (const float*)d_in[4];
    const float* Wk = (const float*)d_in[5];
    const float* bk = (const float*)d_in[6];
    const float* Wv = (const float*)d_in[7];
    const float* bv = (const float*)d_in[8];
    const float* Wo = (const float*)d_in[9];
    const float* bo = (const float*)d_in[10];
    const float* sw = (const float*)d_in[11];
    float* out = (float*)d_out;

    static bool attr_set = false;
    if (!attr_set) {
        cudaFuncSetAttribute(gemm_tc_kernel,
                             cudaFuncAttributeMaxDynamicSharedMemorySize, GSMEM);
        cudaFuncSetAttribute(attn_kernel,
                             cudaFuncAttributeMaxDynamicSharedMemorySize, ASMEM);
        attr_set = true;
    }

    dim3 ggrid(GN / 128, GM / 128);   // (8, 128)
    dim3 swgrid(GN / 32, GK / 32, 4); // (32, 32, 4)

    // 1: W^T splits
    split_wt4_kernel<<<swgrid, 256>>>(Wq, Wk, Wv, Wo);

    // 2,3,4: Q, K, V projections (fp32 A inline-converted; fp16 C)
    gemm_tc_kernel<<<ggrid, 256, GSMEM>>>(query, 0, nullptr, 1, bq);
    gemm_tc_kernel<<<ggrid, 256, GSMEM>>>(key,   1, nullptr, 2, bk);
    gemm_tc_kernel<<<ggrid, 256, GSMEM>>>(value, 2, nullptr, 3, bv);

    // 5: attention (warp per position; 8 positions per CTA)
    float* attn_dst = (out_size >= MAIN_OUT_ELEMS + ATT_ELEMS) ? (out + MAIN_OUT_ELEMS)
                                                               : nullptr;
    attn_kernel<<<NPOS / 8, 256, ASMEM>>>(sw, attn_dst);

    // 6: output projection (fp16 A from g_Xh; fp32 C = d_out)
    gemm_tc_kernel<<<ggrid, 256, GSMEM>>>(nullptr, 3, out, 0, bo);
}